// round 1
// baseline (speedup 1.0000x reference)
#include <cuda_runtime.h>
#include <math_constants.h>

#define NN 50000
#define NE 800000
#define HID 128

// ---------------- scratch (static device globals; no runtime alloc) ----------------
__device__ float g_img_f[NN * HID];
__device__ float g_txt_f[NN * HID];
__device__ float g_z[NN * HID];
__device__ float g_esrc[NN];
__device__ float g_edst[NN];
__device__ float g_emax[NN];
__device__ float g_denom[NN];
__device__ float g_e[NE];

// ---------------- init: zero out, denom; emax = -inf ----------------
__global__ void k_init(float* __restrict__ out, int n_out, int n_nodes) {
    int i = blockIdx.x * blockDim.x + threadIdx.x;
    if (i < n_out) out[i] = 0.f;
    if (i < n_nodes) { g_emax[i] = -CUDART_INF_F; g_denom[i] = 0.f; }
}

// ---------------- SGEMM: C[M,128] = A[M,K] @ B[K,128], fp32 ----------------
// 128x128 block tile, BK=32, 256 threads, 8x8 per thread.
__global__ __launch_bounds__(256, 2)
void k_sgemm(const float* __restrict__ A, const float* __restrict__ B,
             float* __restrict__ C, int M, int K) {
    __shared__ float As[32][132];   // As[k][m], padded
    __shared__ float Bs[32][128];
    int tid = threadIdx.x;
    int m0  = blockIdx.x * 128;
    int tx  = tid & 15;             // col group (cols tx*8..tx*8+7)
    int ty  = tid >> 4;             // row group (rows ty*8..ty*8+7)
    float acc[8][8];
    #pragma unroll
    for (int i = 0; i < 8; ++i)
        #pragma unroll
        for (int j = 0; j < 8; ++j) acc[i][j] = 0.f;

    #pragma unroll 1
    for (int k0 = 0; k0 < K; k0 += 32) {
        #pragma unroll
        for (int i = 0; i < 16; ++i) {             // A tile: 128x32
            int idx = tid + i * 256;               // 0..4095
            int m = idx >> 5, kk = idx & 31;
            float v = (m0 + m < M) ? A[(size_t)(m0 + m) * K + k0 + kk] : 0.f;
            As[kk][m] = v;
        }
        #pragma unroll
        for (int i = 0; i < 16; ++i) {             // B tile: 32x128
            int idx = tid + i * 256;
            int kk = idx >> 7, n = idx & 127;
            Bs[kk][n] = B[(size_t)(k0 + kk) * 128 + n];
        }
        __syncthreads();
        #pragma unroll
        for (int kk = 0; kk < 32; ++kk) {
            float a[8], b[8];
            *(float4*)&a[0] = *(const float4*)&As[kk][ty * 8];
            *(float4*)&a[4] = *(const float4*)&As[kk][ty * 8 + 4];
            *(float4*)&b[0] = *(const float4*)&Bs[kk][tx * 8];
            *(float4*)&b[4] = *(const float4*)&Bs[kk][tx * 8 + 4];
            #pragma unroll
            for (int i = 0; i < 8; ++i)
                #pragma unroll
                for (int j = 0; j < 8; ++j)
                    acc[i][j] = fmaf(a[i], b[j], acc[i][j]);
        }
        __syncthreads();
    }
    #pragma unroll
    for (int i = 0; i < 8; ++i) {
        int m = m0 + ty * 8 + i;
        if (m < M) {
            float4 v0 = make_float4(acc[i][0], acc[i][1], acc[i][2], acc[i][3]);
            float4 v1 = make_float4(acc[i][4], acc[i][5], acc[i][6], acc[i][7]);
            *(float4*)&C[(size_t)m * 128 + tx * 8]     = v0;
            *(float4*)&C[(size_t)m * 128 + tx * 8 + 4] = v1;
        }
    }
}

// ---------------- fused per-node pipeline ----------------
// block = 64 nodes, 256 threads. thread (r = tid/32, c = tid%32) owns
// nodes r*8..r*8+7  x  cols c*4..c*4+3.
struct SmemT {
    float E[64][128];    // embed
    float A[64][128];    // img feat -> img_v
    float B[64][128];    // txt feat -> txt_v
    float H[64][128];    // h1 / h
    float W[32][128];    // weight stage
    float g[64];
};
#define NODE_SMEM_BYTES ((int)sizeof(SmemT))

// acc += Xs(64x128) @ Wg(128x128), Wg row-major in global, streamed via sW.
__device__ __forceinline__ void gemm128(const float* __restrict__ Wg,
                                        const float (*__restrict__ Xs)[128],
                                        float (*__restrict__ sW)[128],
                                        float acc[8][4], int tid, int r, int c) {
    #pragma unroll 1
    for (int k0 = 0; k0 < 128; k0 += 32) {
        __syncthreads();                            // sW reuse / input visibility
        #pragma unroll
        for (int i = 0; i < 16; ++i) {
            int idx = tid + i * 256;                // 0..4095
            ((float*)sW)[idx] = Wg[k0 * 128 + idx];
        }
        __syncthreads();
        #pragma unroll
        for (int kk = 0; kk < 32; ++kk) {
            float4 wv = *(const float4*)&sW[kk][c * 4];
            #pragma unroll
            for (int i = 0; i < 8; ++i) {
                float x = Xs[r * 8 + i][k0 + kk];
                acc[i][0] = fmaf(x, wv.x, acc[i][0]);
                acc[i][1] = fmaf(x, wv.y, acc[i][1]);
                acc[i][2] = fmaf(x, wv.z, acc[i][2]);
                acc[i][3] = fmaf(x, wv.w, acc[i][3]);
            }
        }
    }
}

__device__ __forceinline__ void zero_acc(float acc[8][4]) {
    #pragma unroll
    for (int i = 0; i < 8; ++i)
        #pragma unroll
        for (int j = 0; j < 4; ++j) acc[i][j] = 0.f;
}

__device__ __forceinline__ float warp_sum(float v) {
    #pragma unroll
    for (int off = 16; off > 0; off >>= 1)
        v += __shfl_xor_sync(0xffffffffu, v, off);
    return v;
}

__global__ __launch_bounds__(256, 1)
void k_node(const int* __restrict__ node_id, const float* __restrict__ emb,
            const float* __restrict__ iW1, const float* __restrict__ ib1,
            const float* __restrict__ iW2, const float* __restrict__ ib2,
            const float* __restrict__ iW3, const float* __restrict__ ib3,
            const float* __restrict__ tW1, const float* __restrict__ tb1,
            const float* __restrict__ tW2, const float* __restrict__ tb2,
            const float* __restrict__ tW3, const float* __restrict__ tb3,
            const float* __restrict__ cW,  const float* __restrict__ cb,
            const float* __restrict__ fW,  const float* __restrict__ attn_a,
            int N) {
    extern __shared__ char smem_raw[];
    SmemT& s = *reinterpret_cast<SmemT*>(smem_raw);
    int tid = threadIdx.x;
    int c = tid & 31, r = tid >> 5;
    int base = blockIdx.x * 64;

    // load embed (gather) + img feature
    #pragma unroll
    for (int i = 0; i < 8; ++i) {
        int idx = tid + i * 256;              // float4 index 0..2047
        int n = idx >> 5, c4 = idx & 31;
        int gn = base + n;
        int nid = (gn < N) ? node_id[gn] : 0;
        *(float4*)&s.E[n][c4 * 4] = *(const float4*)&emb[(size_t)nid * 128 + c4 * 4];
        float4 fv = make_float4(0.f, 0.f, 0.f, 0.f);
        if (gn < N) fv = *(const float4*)&g_img_f[(size_t)gn * 128 + c4 * 4];
        *(float4*)&s.A[n][c4 * 4] = fv;
    }

    float acc[8][4];

    // ---- img gate MLP ----
    zero_acc(acc);
    gemm128(iW1,             s.E, s.W, acc, tid, r, c);
    gemm128(iW1 + 128 * 128, s.A, s.W, acc, tid, r, c);
    {
        float4 b = *(const float4*)&ib1[c * 4];
        #pragma unroll
        for (int i = 0; i < 8; ++i) {
            s.H[r * 8 + i][c * 4 + 0] = fmaxf(acc[i][0] + b.x, 0.f);
            s.H[r * 8 + i][c * 4 + 1] = fmaxf(acc[i][1] + b.y, 0.f);
            s.H[r * 8 + i][c * 4 + 2] = fmaxf(acc[i][2] + b.z, 0.f);
            s.H[r * 8 + i][c * 4 + 3] = fmaxf(acc[i][3] + b.w, 0.f);
        }
    }
    zero_acc(acc);
    gemm128(iW2, s.H, s.W, acc, tid, r, c);
    {
        float4 b2 = *(const float4*)&ib2[c * 4];
        float4 w3 = *(const float4*)&iW3[c * 4];
        float b3 = ib3[0];
        #pragma unroll
        for (int i = 0; i < 8; ++i) {
            float loc = fmaxf(acc[i][0] + b2.x, 0.f) * w3.x
                      + fmaxf(acc[i][1] + b2.y, 0.f) * w3.y
                      + fmaxf(acc[i][2] + b2.z, 0.f) * w3.z
                      + fmaxf(acc[i][3] + b2.w, 0.f) * w3.w;
            loc = warp_sum(loc);
            if (c == 0) s.g[r * 8 + i] = 1.f / (1.f + expf(-(loc + b3)));
        }
    }
    __syncthreads();
    // img_v -> s.A
    #pragma unroll
    for (int i = 0; i < 8; ++i) {
        float gv = s.g[r * 8 + i];
        #pragma unroll
        for (int j = 0; j < 4; ++j) {
            float f = s.A[r * 8 + i][c * 4 + j];
            float e = s.E[r * 8 + i][c * 4 + j];
            s.A[r * 8 + i][c * 4 + j] = gv * f + (1.f - gv) * e;
        }
    }
    // load txt feature -> s.B
    #pragma unroll
    for (int i = 0; i < 8; ++i) {
        int idx = tid + i * 256;
        int n = idx >> 5, c4 = idx & 31;
        int gn = base + n;
        float4 fv = make_float4(0.f, 0.f, 0.f, 0.f);
        if (gn < N) fv = *(const float4*)&g_txt_f[(size_t)gn * 128 + c4 * 4];
        *(float4*)&s.B[n][c4 * 4] = fv;
    }

    // ---- txt gate MLP ----
    zero_acc(acc);
    gemm128(tW1,             s.E, s.W, acc, tid, r, c);
    gemm128(tW1 + 128 * 128, s.B, s.W, acc, tid, r, c);
    {
        float4 b = *(const float4*)&tb1[c * 4];
        #pragma unroll
        for (int i = 0; i < 8; ++i) {
            s.H[r * 8 + i][c * 4 + 0] = fmaxf(acc[i][0] + b.x, 0.f);
            s.H[r * 8 + i][c * 4 + 1] = fmaxf(acc[i][1] + b.y, 0.f);
            s.H[r * 8 + i][c * 4 + 2] = fmaxf(acc[i][2] + b.z, 0.f);
            s.H[r * 8 + i][c * 4 + 3] = fmaxf(acc[i][3] + b.w, 0.f);
        }
    }
    zero_acc(acc);
    gemm128(tW2, s.H, s.W, acc, tid, r, c);
    {
        float4 b2 = *(const float4*)&tb2[c * 4];
        float4 w3 = *(const float4*)&tW3[c * 4];
        float b3 = tb3[0];
        #pragma unroll
        for (int i = 0; i < 8; ++i) {
            float loc = fmaxf(acc[i][0] + b2.x, 0.f) * w3.x
                      + fmaxf(acc[i][1] + b2.y, 0.f) * w3.y
                      + fmaxf(acc[i][2] + b2.z, 0.f) * w3.z
                      + fmaxf(acc[i][3] + b2.w, 0.f) * w3.w;
            loc = warp_sum(loc);
            if (c == 0) s.g[r * 8 + i] = 1.f / (1.f + expf(-(loc + b3)));
        }
    }
    __syncthreads();
    // txt_v -> s.B
    #pragma unroll
    for (int i = 0; i < 8; ++i) {
        float gv = s.g[r * 8 + i];
        #pragma unroll
        for (int j = 0; j < 4; ++j) {
            float f = s.B[r * 8 + i][c * 4 + j];
            float e = s.E[r * 8 + i][c * 4 + j];
            s.B[r * 8 + i][c * 4 + j] = gv * f + (1.f - gv) * e;
        }
    }

    // ---- comb gate (vector, no activation) + h ----
    zero_acc(acc);
    gemm128(cW,             s.A, s.W, acc, tid, r, c);
    gemm128(cW + 128 * 128, s.B, s.W, acc, tid, r, c);
    {
        float4 b = *(const float4*)&cb[c * 4];
        float bb[4] = {b.x, b.y, b.z, b.w};
        #pragma unroll
        for (int i = 0; i < 8; ++i)
            #pragma unroll
            for (int j = 0; j < 4; ++j) {
                float gate = acc[i][j] + bb[j];
                float iv = s.A[r * 8 + i][c * 4 + j];
                float tv = s.B[r * 8 + i][c * 4 + j];
                s.H[r * 8 + i][c * 4 + j] = gate * iv + (1.f - gate) * tv;
            }
    }

    // ---- z = h @ fc_W ; attention logits ----
    zero_acc(acc);
    gemm128(fW, s.H, s.W, acc, tid, r, c);
    {
        float4 a1 = *(const float4*)&attn_a[c * 4];
        float4 a2 = *(const float4*)&attn_a[128 + c * 4];
        #pragma unroll
        for (int i = 0; i < 8; ++i) {
            int gn = base + r * 8 + i;
            if (gn < N) {
                float4 zv = make_float4(acc[i][0], acc[i][1], acc[i][2], acc[i][3]);
                *(float4*)&g_z[(size_t)gn * 128 + c * 4] = zv;
            }
            float l1 = acc[i][0] * a1.x + acc[i][1] * a1.y + acc[i][2] * a1.z + acc[i][3] * a1.w;
            float l2 = acc[i][0] * a2.x + acc[i][1] * a2.y + acc[i][2] * a2.z + acc[i][3] * a2.w;
            l1 = warp_sum(l1);
            l2 = warp_sum(l2);
            if (c == 0 && gn < N) { g_esrc[gn] = l1; g_edst[gn] = l2; }
        }
    }
}

// ---------------- edge phase ----------------
__device__ __forceinline__ void atomicMaxF(float* addr, float v) {
    if (v >= 0.f) atomicMax((int*)addr, __float_as_int(v));
    else          atomicMin((unsigned int*)addr, __float_as_uint(v));
}

__global__ void k_edge_max(const int* __restrict__ src, const int* __restrict__ dst, int E) {
    int i = blockIdx.x * blockDim.x + threadIdx.x;
    if (i >= E) return;
    float e = g_esrc[src[i]] + g_edst[dst[i]];
    e = (e >= 0.f) ? e : 0.01f * e;          // leaky relu 0.01
    g_e[i] = e;
    atomicMaxF(&g_emax[dst[i]], e);
}

__global__ void k_edge_exp(const int* __restrict__ dst, int E) {
    int i = blockIdx.x * blockDim.x + threadIdx.x;
    if (i >= E) return;
    int d = dst[i];
    float ex = expf(g_e[i] - g_emax[d]);
    g_e[i] = ex;
    atomicAdd(&g_denom[d], ex);
}

// one warp per edge; lane handles 4 columns
__global__ void k_edge_agg(const int* __restrict__ src, const int* __restrict__ dst,
                           float* __restrict__ out, int E) {
    int w = (int)((blockIdx.x * (size_t)blockDim.x + threadIdx.x) >> 5);
    int lane = threadIdx.x & 31;
    if (w >= E) return;
    int sN = src[w], d = dst[w];
    float alpha = g_e[w] / fmaxf(g_denom[d], 1e-20f);
    float4 zv = *(const float4*)&g_z[(size_t)sN * 128 + lane * 4];
    float* o = out + (size_t)d * 128 + lane * 4;
    atomicAdd(o + 0, alpha * zv.x);
    atomicAdd(o + 1, alpha * zv.y);
    atomicAdd(o + 2, alpha * zv.z);
    atomicAdd(o + 3, alpha * zv.w);
}

// ---------------- launch ----------------
extern "C" void kernel_launch(void* const* d_in, const int* in_sizes, int n_in,
                              void* d_out, int out_size) {
    const int*   node_id = (const int*)  d_in[0];
    const float* img_h   = (const float*)d_in[1];
    const float* txt_h   = (const float*)d_in[2];
    const int*   src     = (const int*)  d_in[3];
    const int*   dst     = (const int*)  d_in[4];
    const float* emb     = (const float*)d_in[5];
    const float* W_img   = (const float*)d_in[6];
    const float* iW1     = (const float*)d_in[7];
    const float* ib1     = (const float*)d_in[8];
    const float* iW2     = (const float*)d_in[9];
    const float* ib2     = (const float*)d_in[10];
    const float* iW3     = (const float*)d_in[11];
    const float* ib3     = (const float*)d_in[12];
    const float* W_txt   = (const float*)d_in[13];
    const float* tW1     = (const float*)d_in[14];
    const float* tb1     = (const float*)d_in[15];
    const float* tW2     = (const float*)d_in[16];
    const float* tb2     = (const float*)d_in[17];
    const float* tW3     = (const float*)d_in[18];
    const float* tb3     = (const float*)d_in[19];
    const float* cW      = (const float*)d_in[20];
    const float* cb      = (const float*)d_in[21];
    const float* fW      = (const float*)d_in[22];
    const float* attn_a  = (const float*)d_in[23];

    int N = in_sizes[0];
    int E = in_sizes[3];
    int IMG_D = in_sizes[1] / N;
    int TXT_D = in_sizes[2] / N;
    float* out = (float*)d_out;

    float *p_img_f, *p_txt_f;
    cudaGetSymbolAddress((void**)&p_img_f, g_img_f);
    cudaGetSymbolAddress((void**)&p_txt_f, g_txt_f);

    cudaFuncSetAttribute(k_node, cudaFuncAttributeMaxDynamicSharedMemorySize, NODE_SMEM_BYTES);

    k_init<<<(N * HID + 255) / 256, 256>>>(out, N * HID, N);

    k_sgemm<<<(N + 127) / 128, 256>>>(img_h, W_img, p_img_f, N, IMG_D);
    k_sgemm<<<(N + 127) / 128, 256>>>(txt_h, W_txt, p_txt_f, N, TXT_D);

    k_node<<<(N + 63) / 64, 256, NODE_SMEM_BYTES>>>(
        node_id, emb,
        iW1, ib1, iW2, ib2, iW3, ib3,
        tW1, tb1, tW2, tb2, tW3, tb3,
        cW, cb, fW, attn_a, N);

    k_edge_max<<<(E + 255) / 256, 256>>>(src, dst, E);
    k_edge_exp<<<(E + 255) / 256, 256>>>(dst, E);
    k_edge_agg<<<(E * 32 + 255) / 256, 256>>>(src, dst, out, E);
}

// round 2
// speedup vs baseline: 1.1154x; 1.1154x over previous
#include <cuda_runtime.h>
#include <math_constants.h>

#define NN 50000
#define NE 800000
#define HID 128

// ---------------- scratch (static device globals; no runtime alloc) ----------------
__device__ float g_img_f[NN * HID];
__device__ float g_txt_f[NN * HID];
__device__ float g_z[NN * HID];
__device__ float g_esrc[NN];
__device__ float g_edst[NN];
__device__ float g_emax[NN];
__device__ float g_denom[NN];
__device__ float g_e[NE];

// ---------------- init: zero out, denom; emax = -inf ----------------
__global__ void k_init(float* __restrict__ out, int n_out, int n_nodes) {
    int i = blockIdx.x * blockDim.x + threadIdx.x;
    if (i < n_out) out[i] = 0.f;
    if (i < n_nodes) { g_emax[i] = -CUDART_INF_F; g_denom[i] = 0.f; }
}

// ---------------- SGEMM: C[M,128] = A[M,K] @ B[K,128], fp32 ----------------
// 128x128 block tile, BK=32, 256 threads, 8x8 per thread. (unchanged from R1)
__global__ __launch_bounds__(256, 2)
void k_sgemm(const float* __restrict__ A, const float* __restrict__ B,
             float* __restrict__ C, int M, int K) {
    __shared__ float As[32][132];   // As[k][m], padded
    __shared__ float Bs[32][128];
    int tid = threadIdx.x;
    int m0  = blockIdx.x * 128;
    int tx  = tid & 15;
    int ty  = tid >> 4;
    float acc[8][8];
    #pragma unroll
    for (int i = 0; i < 8; ++i)
        #pragma unroll
        for (int j = 0; j < 8; ++j) acc[i][j] = 0.f;

    #pragma unroll 1
    for (int k0 = 0; k0 < K; k0 += 32) {
        #pragma unroll
        for (int i = 0; i < 16; ++i) {
            int idx = tid + i * 256;
            int m = idx >> 5, kk = idx & 31;
            float v = (m0 + m < M) ? A[(size_t)(m0 + m) * K + k0 + kk] : 0.f;
            As[kk][m] = v;
        }
        #pragma unroll
        for (int i = 0; i < 16; ++i) {
            int idx = tid + i * 256;
            int kk = idx >> 7, n = idx & 127;
            Bs[kk][n] = B[(size_t)(k0 + kk) * 128 + n];
        }
        __syncthreads();
        #pragma unroll
        for (int kk = 0; kk < 32; ++kk) {
            float a[8], b[8];
            *(float4*)&a[0] = *(const float4*)&As[kk][ty * 8];
            *(float4*)&a[4] = *(const float4*)&As[kk][ty * 8 + 4];
            *(float4*)&b[0] = *(const float4*)&Bs[kk][tx * 8];
            *(float4*)&b[4] = *(const float4*)&Bs[kk][tx * 8 + 4];
            #pragma unroll
            for (int i = 0; i < 8; ++i)
                #pragma unroll
                for (int j = 0; j < 8; ++j)
                    acc[i][j] = fmaf(a[i], b[j], acc[i][j]);
        }
        __syncthreads();
    }
    #pragma unroll
    for (int i = 0; i < 8; ++i) {
        int m = m0 + ty * 8 + i;
        if (m < M) {
            float4 v0 = make_float4(acc[i][0], acc[i][1], acc[i][2], acc[i][3]);
            float4 v1 = make_float4(acc[i][4], acc[i][5], acc[i][6], acc[i][7]);
            *(float4*)&C[(size_t)m * 128 + tx * 8]     = v0;
            *(float4*)&C[(size_t)m * 128 + tx * 8 + 4] = v1;
        }
    }
}

// ---------------- fused per-node pipeline (v2) ----------------
// 32 nodes / block, 256 threads, smem 64KB -> 3 CTAs/SM.
// thread (r = tid/32, c = tid%32) owns rows r*4..r*4+3 x cols c*4..c*4+3.
// Weights read straight from global (L1-hot across co-resident CTAs).
struct SmemT {
    float E[32][128];
    float A[32][128];
    float B[32][128];
    float H[32][128];
    float g[32];
};
#define NODE_SMEM_BYTES ((int)sizeof(SmemT))

// acc += Xs(32x128) @ Wg(128x128). W read via __ldg float4, X via broadcast LDS.128.
__device__ __forceinline__ void gemm32(const float* __restrict__ Wg,
                                       const float (*__restrict__ Xs)[128],
                                       float acc[4][4], int r, int c) {
    #pragma unroll 1
    for (int k0 = 0; k0 < 128; k0 += 4) {
        float4 xv[4];
        #pragma unroll
        for (int i = 0; i < 4; ++i)
            xv[i] = *(const float4*)&Xs[r * 4 + i][k0];
        #pragma unroll
        for (int q = 0; q < 4; ++q) {
            float4 wv = __ldg((const float4*)&Wg[(k0 + q) * 128 + c * 4]);
            #pragma unroll
            for (int i = 0; i < 4; ++i) {
                float x = (q == 0) ? xv[i].x : (q == 1) ? xv[i].y : (q == 2) ? xv[i].z : xv[i].w;
                acc[i][0] = fmaf(x, wv.x, acc[i][0]);
                acc[i][1] = fmaf(x, wv.y, acc[i][1]);
                acc[i][2] = fmaf(x, wv.z, acc[i][2]);
                acc[i][3] = fmaf(x, wv.w, acc[i][3]);
            }
        }
    }
}

__device__ __forceinline__ void zero_acc(float acc[4][4]) {
    #pragma unroll
    for (int i = 0; i < 4; ++i)
        #pragma unroll
        for (int j = 0; j < 4; ++j) acc[i][j] = 0.f;
}

__device__ __forceinline__ float warp_sum(float v) {
    #pragma unroll
    for (int off = 16; off > 0; off >>= 1)
        v += __shfl_xor_sync(0xffffffffu, v, off);
    return v;
}

__global__ __launch_bounds__(256, 3)
void k_node(const int* __restrict__ node_id, const float* __restrict__ emb,
            const float* __restrict__ iW1, const float* __restrict__ ib1,
            const float* __restrict__ iW2, const float* __restrict__ ib2,
            const float* __restrict__ iW3, const float* __restrict__ ib3,
            const float* __restrict__ tW1, const float* __restrict__ tb1,
            const float* __restrict__ tW2, const float* __restrict__ tb2,
            const float* __restrict__ tW3, const float* __restrict__ tb3,
            const float* __restrict__ cW,  const float* __restrict__ cb,
            const float* __restrict__ fW,  const float* __restrict__ attn_a,
            int N) {
    extern __shared__ char smem_raw[];
    SmemT& s = *reinterpret_cast<SmemT*>(smem_raw);
    int tid = threadIdx.x;
    int c = tid & 31, r = tid >> 5;
    int base = blockIdx.x * 32;

    // ---- load embed (gather) + img feature + txt feature ----
    #pragma unroll
    for (int it = 0; it < 4; ++it) {
        int idx = tid + it * 256;             // float4 index 0..1023
        int n = idx >> 5, c4 = idx & 31;
        int gn = base + n;
        int nid = (gn < N) ? node_id[gn] : 0;
        *(float4*)&s.E[n][c4 * 4] = *(const float4*)&emb[(size_t)nid * 128 + c4 * 4];
        float4 iv = make_float4(0.f, 0.f, 0.f, 0.f);
        float4 tv = make_float4(0.f, 0.f, 0.f, 0.f);
        if (gn < N) {
            iv = *(const float4*)&g_img_f[(size_t)gn * 128 + c4 * 4];
            tv = *(const float4*)&g_txt_f[(size_t)gn * 128 + c4 * 4];
        }
        *(float4*)&s.A[n][c4 * 4] = iv;
        *(float4*)&s.B[n][c4 * 4] = tv;
    }
    __syncthreads();

    float acc[4][4];

    // ==== img gate MLP: h1 ====
    zero_acc(acc);
    gemm32(iW1,             s.E, acc, r, c);
    gemm32(iW1 + 128 * 128, s.A, acc, r, c);
    {
        float4 b = __ldg((const float4*)&ib1[c * 4]);
        #pragma unroll
        for (int i = 0; i < 4; ++i) {
            s.H[r * 4 + i][c * 4 + 0] = fmaxf(acc[i][0] + b.x, 0.f);
            s.H[r * 4 + i][c * 4 + 1] = fmaxf(acc[i][1] + b.y, 0.f);
            s.H[r * 4 + i][c * 4 + 2] = fmaxf(acc[i][2] + b.z, 0.f);
            s.H[r * 4 + i][c * 4 + 3] = fmaxf(acc[i][3] + b.w, 0.f);
        }
    }
    __syncthreads();

    // ==== img gate MLP: h2 + sigmoid scalar ====
    zero_acc(acc);
    gemm32(iW2, s.H, acc, r, c);
    {
        float4 b2 = __ldg((const float4*)&ib2[c * 4]);
        float4 w3 = __ldg((const float4*)&iW3[c * 4]);
        float b3 = __ldg(ib3);
        #pragma unroll
        for (int i = 0; i < 4; ++i) {
            float loc = fmaxf(acc[i][0] + b2.x, 0.f) * w3.x
                      + fmaxf(acc[i][1] + b2.y, 0.f) * w3.y
                      + fmaxf(acc[i][2] + b2.z, 0.f) * w3.z
                      + fmaxf(acc[i][3] + b2.w, 0.f) * w3.w;
            loc = warp_sum(loc);
            if (c == 0) s.g[r * 4 + i] = 1.f / (1.f + expf(-(loc + b3)));
        }
    }
    __syncthreads();

    // ---- img_v -> s.A ----
    #pragma unroll
    for (int i = 0; i < 4; ++i) {
        float gv = s.g[r * 4 + i];
        float4 av = *(const float4*)&s.A[r * 4 + i][c * 4];
        float4 ev = *(const float4*)&s.E[r * 4 + i][c * 4];
        av.x = gv * av.x + (1.f - gv) * ev.x;
        av.y = gv * av.y + (1.f - gv) * ev.y;
        av.z = gv * av.z + (1.f - gv) * ev.z;
        av.w = gv * av.w + (1.f - gv) * ev.w;
        *(float4*)&s.A[r * 4 + i][c * 4] = av;
    }

    // ==== txt gate MLP: h1 ====  (A update above doesn't touch E/B/H; no barrier needed
    // before the gemms read E,B; H writes below are to this thread's own block and the
    // previous H readers all passed the barrier after the img-g epilogue)
    zero_acc(acc);
    gemm32(tW1,             s.E, acc, r, c);
    gemm32(tW1 + 128 * 128, s.B, acc, r, c);
    {
        float4 b = __ldg((const float4*)&tb1[c * 4]);
        #pragma unroll
        for (int i = 0; i < 4; ++i) {
            s.H[r * 4 + i][c * 4 + 0] = fmaxf(acc[i][0] + b.x, 0.f);
            s.H[r * 4 + i][c * 4 + 1] = fmaxf(acc[i][1] + b.y, 0.f);
            s.H[r * 4 + i][c * 4 + 2] = fmaxf(acc[i][2] + b.z, 0.f);
            s.H[r * 4 + i][c * 4 + 3] = fmaxf(acc[i][3] + b.w, 0.f);
        }
    }
    __syncthreads();

    // ==== txt gate MLP: h2 + sigmoid scalar ====
    zero_acc(acc);
    gemm32(tW2, s.H, acc, r, c);
    {
        float4 b2 = __ldg((const float4*)&tb2[c * 4]);
        float4 w3 = __ldg((const float4*)&tW3[c * 4]);
        float b3 = __ldg(tb3);
        #pragma unroll
        for (int i = 0; i < 4; ++i) {
            float loc = fmaxf(acc[i][0] + b2.x, 0.f) * w3.x
                      + fmaxf(acc[i][1] + b2.y, 0.f) * w3.y
                      + fmaxf(acc[i][2] + b2.z, 0.f) * w3.z
                      + fmaxf(acc[i][3] + b2.w, 0.f) * w3.w;
            loc = warp_sum(loc);
            if (c == 0) s.g[r * 4 + i] = 1.f / (1.f + expf(-(loc + b3)));
        }
    }
    __syncthreads();

    // ---- txt_v -> s.B ----
    #pragma unroll
    for (int i = 0; i < 4; ++i) {
        float gv = s.g[r * 4 + i];
        float4 bv = *(const float4*)&s.B[r * 4 + i][c * 4];
        float4 ev = *(const float4*)&s.E[r * 4 + i][c * 4];
        bv.x = gv * bv.x + (1.f - gv) * ev.x;
        bv.y = gv * bv.y + (1.f - gv) * ev.y;
        bv.z = gv * bv.z + (1.f - gv) * ev.z;
        bv.w = gv * bv.w + (1.f - gv) * ev.w;
        *(float4*)&s.B[r * 4 + i][c * 4] = bv;
    }
    __syncthreads();   // B (and A) fully updated before comb gemms read them

    // ==== comb gate (linear) + h ====
    zero_acc(acc);
    gemm32(cW,             s.A, acc, r, c);
    gemm32(cW + 128 * 128, s.B, acc, r, c);
    {
        float4 b = __ldg((const float4*)&cb[c * 4]);
        #pragma unroll
        for (int i = 0; i < 4; ++i) {
            float4 av = *(const float4*)&s.A[r * 4 + i][c * 4];
            float4 bv = *(const float4*)&s.B[r * 4 + i][c * 4];
            float g0 = acc[i][0] + b.x;
            float g1 = acc[i][1] + b.y;
            float g2 = acc[i][2] + b.z;
            float g3 = acc[i][3] + b.w;
            s.H[r * 4 + i][c * 4 + 0] = g0 * av.x + (1.f - g0) * bv.x;
            s.H[r * 4 + i][c * 4 + 1] = g1 * av.y + (1.f - g1) * bv.y;
            s.H[r * 4 + i][c * 4 + 2] = g2 * av.z + (1.f - g2) * bv.z;
            s.H[r * 4 + i][c * 4 + 3] = g3 * av.w + (1.f - g3) * bv.w;
        }
    }
    __syncthreads();

    // ==== z = h @ fc_W ; attention logits ====
    zero_acc(acc);
    gemm32(fW, s.H, acc, r, c);
    {
        float4 a1 = __ldg((const float4*)&attn_a[c * 4]);
        float4 a2 = __ldg((const float4*)&attn_a[128 + c * 4]);
        #pragma unroll
        for (int i = 0; i < 4; ++i) {
            int gn = base + r * 4 + i;
            if (gn < N) {
                float4 zv = make_float4(acc[i][0], acc[i][1], acc[i][2], acc[i][3]);
                *(float4*)&g_z[(size_t)gn * 128 + c * 4] = zv;
            }
            float l1 = acc[i][0] * a1.x + acc[i][1] * a1.y + acc[i][2] * a1.z + acc[i][3] * a1.w;
            float l2 = acc[i][0] * a2.x + acc[i][1] * a2.y + acc[i][2] * a2.z + acc[i][3] * a2.w;
            l1 = warp_sum(l1);
            l2 = warp_sum(l2);
            if (c == 0 && gn < N) { g_esrc[gn] = l1; g_edst[gn] = l2; }
        }
    }
}

// ---------------- edge phase ----------------
__device__ __forceinline__ void atomicMaxF(float* addr, float v) {
    if (v >= 0.f) atomicMax((int*)addr, __float_as_int(v));
    else          atomicMin((unsigned int*)addr, __float_as_uint(v));
}

__global__ void k_edge_max(const int* __restrict__ src, const int* __restrict__ dst, int E) {
    int i = blockIdx.x * blockDim.x + threadIdx.x;
    if (i >= E) return;
    float e = g_esrc[src[i]] + g_edst[dst[i]];
    e = (e >= 0.f) ? e : 0.01f * e;          // leaky relu 0.01
    g_e[i] = e;
    atomicMaxF(&g_emax[dst[i]], e);
}

__global__ void k_edge_exp(const int* __restrict__ dst, int E) {
    int i = blockIdx.x * blockDim.x + threadIdx.x;
    if (i >= E) return;
    int d = dst[i];
    float ex = expf(g_e[i] - g_emax[d]);
    g_e[i] = ex;
    atomicAdd(&g_denom[d], ex);
}

// one warp per edge; lane handles 4 columns via one red.v4
__device__ __forceinline__ void redAdd4(float* addr, float4 v) {
    asm volatile("red.global.add.v4.f32 [%0], {%1, %2, %3, %4};"
                 :: "l"(addr), "f"(v.x), "f"(v.y), "f"(v.z), "f"(v.w) : "memory");
}

__global__ void k_edge_agg(const int* __restrict__ src, const int* __restrict__ dst,
                           float* __restrict__ out, int E) {
    int w = (int)((blockIdx.x * (size_t)blockDim.x + threadIdx.x) >> 5);
    int lane = threadIdx.x & 31;
    if (w >= E) return;
    int sN = src[w], d = dst[w];
    float alpha = g_e[w] / fmaxf(g_denom[d], 1e-20f);
    float4 zv = *(const float4*)&g_z[(size_t)sN * 128 + lane * 4];
    zv.x *= alpha; zv.y *= alpha; zv.z *= alpha; zv.w *= alpha;
    redAdd4(out + (size_t)d * 128 + lane * 4, zv);
}

// ---------------- launch ----------------
extern "C" void kernel_launch(void* const* d_in, const int* in_sizes, int n_in,
                              void* d_out, int out_size) {
    const int*   node_id = (const int*)  d_in[0];
    const float* img_h   = (const float*)d_in[1];
    const float* txt_h   = (const float*)d_in[2];
    const int*   src     = (const int*)  d_in[3];
    const int*   dst     = (const int*)  d_in[4];
    const float* emb     = (const float*)d_in[5];
    const float* W_img   = (const float*)d_in[6];
    const float* iW1     = (const float*)d_in[7];
    const float* ib1     = (const float*)d_in[8];
    const float* iW2     = (const float*)d_in[9];
    const float* ib2     = (const float*)d_in[10];
    const float* iW3     = (const float*)d_in[11];
    const float* ib3     = (const float*)d_in[12];
    const float* W_txt   = (const float*)d_in[13];
    const float* tW1     = (const float*)d_in[14];
    const float* tb1     = (const float*)d_in[15];
    const float* tW2     = (const float*)d_in[16];
    const float* tb2     = (const float*)d_in[17];
    const float* tW3     = (const float*)d_in[18];
    const float* tb3     = (const float*)d_in[19];
    const float* cW      = (const float*)d_in[20];
    const float* cb      = (const float*)d_in[21];
    const float* fW      = (const float*)d_in[22];
    const float* attn_a  = (const float*)d_in[23];

    int N = in_sizes[0];
    int E = in_sizes[3];
    int IMG_D = in_sizes[1] / N;
    int TXT_D = in_sizes[2] / N;
    float* out = (float*)d_out;

    float *p_img_f, *p_txt_f;
    cudaGetSymbolAddress((void**)&p_img_f, g_img_f);
    cudaGetSymbolAddress((void**)&p_txt_f, g_txt_f);

    cudaFuncSetAttribute(k_node, cudaFuncAttributeMaxDynamicSharedMemorySize, NODE_SMEM_BYTES);

    k_init<<<(N * HID + 255) / 256, 256>>>(out, N * HID, N);

    k_sgemm<<<(N + 127) / 128, 256>>>(img_h, W_img, p_img_f, N, IMG_D);
    k_sgemm<<<(N + 127) / 128, 256>>>(txt_h, W_txt, p_txt_f, N, TXT_D);

    k_node<<<(N + 31) / 32, 256, NODE_SMEM_BYTES>>>(
        node_id, emb,
        iW1, ib1, iW2, ib2, iW3, ib3,
        tW1, tb1, tW2, tb2, tW3, tb3,
        cW, cb, fW, attn_a, N);

    k_edge_max<<<(E + 255) / 256, 256>>>(src, dst, E);
    k_edge_exp<<<(E + 255) / 256, 256>>>(dst, E);
    k_edge_agg<<<(E * 32 + 255) / 256, 256>>>(src, dst, out, E);
}

// round 3
// speedup vs baseline: 1.4390x; 1.2902x over previous
#include <cuda_runtime.h>
#include <math_constants.h>

#define NN 50000
#define NE 800000
#define HID 128

// ---------------- scratch ----------------
__device__ float g_img_f[NN * HID];
__device__ float g_txt_f[NN * HID];
__device__ float g_z[NN * HID];
__device__ float g_esrc[NN];
__device__ float g_edst[NN];
__device__ float g_emax[NN];
__device__ float g_denom[NN];
__device__ float g_e[NE];

// ---------------- init ----------------
__global__ void k_init(float* __restrict__ out, int n_out, int n_nodes) {
    int i = blockIdx.x * blockDim.x + threadIdx.x;
    if (i < n_out) out[i] = 0.f;
    if (i < n_nodes) { g_emax[i] = -CUDART_INF_F; g_denom[i] = 0.f; }
}

// ================= TF32 tensor-core GEMM with 3xTF32 compensation =================
// C[M,128] = A[M,K] @ B[K,128], fp32 in/out, ~fp32 accuracy.
// Block: 128 rows x 128 cols, BK=32, 256 threads (8 warps as 2x4 of 64x32 warptiles).

__device__ __forceinline__ unsigned cvt_tf32(float x) {
    unsigned r; asm("cvt.rna.tf32.f32 %0, %1;" : "=r"(r) : "f"(x)); return r;
}

__device__ __forceinline__ void mma_tf32(float c[4], unsigned a0, unsigned a1,
                                         unsigned a2, unsigned a3,
                                         unsigned b0, unsigned b1) {
    asm volatile(
        "mma.sync.aligned.m16n8k8.row.col.f32.tf32.tf32.f32 "
        "{%0,%1,%2,%3}, {%4,%5,%6,%7}, {%8,%9}, {%0,%1,%2,%3};"
        : "+f"(c[0]), "+f"(c[1]), "+f"(c[2]), "+f"(c[3])
        : "r"(a0), "r"(a1), "r"(a2), "r"(a3), "r"(b0), "r"(b1));
}

#define AS_LD 132   // padded leading dim for A tiles ([k][m])

struct MmaSmem {
    unsigned Ahi[32][AS_LD];
    unsigned Alo[32][AS_LD];
    unsigned Bhi[32][128];
    unsigned Blo[32][128];
};
#define MMA_SMEM_BYTES ((int)sizeof(MmaSmem))

__global__ __launch_bounds__(256, 2)
void k_mma_gemm(const float* __restrict__ A, const float* __restrict__ B,
                float* __restrict__ C, int M, int K) {
    extern __shared__ char smem_raw[];
    MmaSmem& s = *reinterpret_cast<MmaSmem*>(smem_raw);
    int tid  = threadIdx.x;
    int warp = tid >> 5, lane = tid & 31;
    int wm = warp & 1;          // 0..1 : 64-row slab
    int wn = warp >> 1;         // 0..3 : 32-col slab
    int grp = lane >> 2, q = lane & 3;
    int m0 = blockIdx.x * 128;

    float acc[4][4][4];         // [mt][nt][frag]
    #pragma unroll
    for (int i = 0; i < 4; ++i)
        #pragma unroll
        for (int j = 0; j < 4; ++j)
            #pragma unroll
            for (int k = 0; k < 4; ++k) acc[i][j][k] = 0.f;

    #pragma unroll 1
    for (int k0 = 0; k0 < K; k0 += 32) {
        // ---- stage A tile 128x32 (convert to hi/lo tf32, store [k][m]) ----
        #pragma unroll
        for (int i = 0; i < 4; ++i) {
            int f4 = tid + i * 256;           // 0..1023
            int r = f4 >> 3, c4 = f4 & 7;     // row r, k-group c4
            float4 v = make_float4(0.f, 0.f, 0.f, 0.f);
            if (m0 + r < M) v = *(const float4*)&A[(size_t)(m0 + r) * K + k0 + c4 * 4];
            float vv[4] = {v.x, v.y, v.z, v.w};
            #pragma unroll
            for (int j = 0; j < 4; ++j) {
                unsigned hi = cvt_tf32(vv[j]);
                float lo = vv[j] - __uint_as_float(hi);
                s.Ahi[c4 * 4 + j][r] = hi;
                s.Alo[c4 * 4 + j][r] = cvt_tf32(lo);
            }
        }
        // ---- stage B tile 32x128 ----
        #pragma unroll
        for (int i = 0; i < 4; ++i) {
            int f4 = tid + i * 256;
            int kk = f4 >> 5, c = f4 & 31;
            float4 v = *(const float4*)&B[(size_t)(k0 + kk) * 128 + c * 4];
            float vv[4] = {v.x, v.y, v.z, v.w};
            unsigned hi4[4], lo4[4];
            #pragma unroll
            for (int j = 0; j < 4; ++j) {
                hi4[j] = cvt_tf32(vv[j]);
                lo4[j] = cvt_tf32(vv[j] - __uint_as_float(hi4[j]));
            }
            *(uint4*)&s.Bhi[kk][c * 4] = make_uint4(hi4[0], hi4[1], hi4[2], hi4[3]);
            *(uint4*)&s.Blo[kk][c * 4] = make_uint4(lo4[0], lo4[1], lo4[2], lo4[3]);
        }
        __syncthreads();

        #pragma unroll
        for (int kc = 0; kc < 4; ++kc) {
            int kq = kc * 8 + q;
            unsigned af[4][4], bh[4][2], bl[4][2];
            #pragma unroll
            for (int mt = 0; mt < 4; ++mt) {
                int m = wm * 64 + mt * 16 + grp;
                af[mt][0] = s.Ahi[kq][m];
                af[mt][1] = s.Ahi[kq][m + 8];
                af[mt][2] = s.Ahi[kq + 4][m];
                af[mt][3] = s.Ahi[kq + 4][m + 8];
            }
            #pragma unroll
            for (int nt = 0; nt < 4; ++nt) {
                int n = wn * 32 + nt * 8 + grp;
                bh[nt][0] = s.Bhi[kq][n];  bh[nt][1] = s.Bhi[kq + 4][n];
                bl[nt][0] = s.Blo[kq][n];  bl[nt][1] = s.Blo[kq + 4][n];
            }
            // Ahi*Bhi + Ahi*Blo
            #pragma unroll
            for (int mt = 0; mt < 4; ++mt)
                #pragma unroll
                for (int nt = 0; nt < 4; ++nt) {
                    mma_tf32(acc[mt][nt], af[mt][0], af[mt][1], af[mt][2], af[mt][3],
                             bh[nt][0], bh[nt][1]);
                    mma_tf32(acc[mt][nt], af[mt][0], af[mt][1], af[mt][2], af[mt][3],
                             bl[nt][0], bl[nt][1]);
                }
            // Alo*Bhi (reload A frags as lo)
            #pragma unroll
            for (int mt = 0; mt < 4; ++mt) {
                int m = wm * 64 + mt * 16 + grp;
                af[mt][0] = s.Alo[kq][m];
                af[mt][1] = s.Alo[kq][m + 8];
                af[mt][2] = s.Alo[kq + 4][m];
                af[mt][3] = s.Alo[kq + 4][m + 8];
            }
            #pragma unroll
            for (int mt = 0; mt < 4; ++mt)
                #pragma unroll
                for (int nt = 0; nt < 4; ++nt)
                    mma_tf32(acc[mt][nt], af[mt][0], af[mt][1], af[mt][2], af[mt][3],
                             bh[nt][0], bh[nt][1]);
        }
        __syncthreads();
    }

    // ---- store C ----
    #pragma unroll
    for (int mt = 0; mt < 4; ++mt) {
        int m = m0 + wm * 64 + mt * 16 + grp;
        #pragma unroll
        for (int nt = 0; nt < 4; ++nt) {
            int n = wn * 32 + nt * 8 + 2 * q;
            if (m < M)
                *(float2*)&C[(size_t)m * 128 + n] = make_float2(acc[mt][nt][0], acc[mt][nt][1]);
            if (m + 8 < M)
                *(float2*)&C[(size_t)(m + 8) * 128 + n] = make_float2(acc[mt][nt][2], acc[mt][nt][3]);
        }
    }
}

// ---------------- fused per-node pipeline (unchanged from R2) ----------------
struct SmemT {
    float E[32][128];
    float A[32][128];
    float B[32][128];
    float H[32][128];
    float g[32];
};
#define NODE_SMEM_BYTES ((int)sizeof(SmemT))

__device__ __forceinline__ void gemm32(const float* __restrict__ Wg,
                                       const float (*__restrict__ Xs)[128],
                                       float acc[4][4], int r, int c) {
    #pragma unroll 1
    for (int k0 = 0; k0 < 128; k0 += 4) {
        float4 xv[4];
        #pragma unroll
        for (int i = 0; i < 4; ++i)
            xv[i] = *(const float4*)&Xs[r * 4 + i][k0];
        #pragma unroll
        for (int q = 0; q < 4; ++q) {
            float4 wv = __ldg((const float4*)&Wg[(k0 + q) * 128 + c * 4]);
            #pragma unroll
            for (int i = 0; i < 4; ++i) {
                float x = (q == 0) ? xv[i].x : (q == 1) ? xv[i].y : (q == 2) ? xv[i].z : xv[i].w;
                acc[i][0] = fmaf(x, wv.x, acc[i][0]);
                acc[i][1] = fmaf(x, wv.y, acc[i][1]);
                acc[i][2] = fmaf(x, wv.z, acc[i][2]);
                acc[i][3] = fmaf(x, wv.w, acc[i][3]);
            }
        }
    }
}

__device__ __forceinline__ void zero_acc(float acc[4][4]) {
    #pragma unroll
    for (int i = 0; i < 4; ++i)
        #pragma unroll
        for (int j = 0; j < 4; ++j) acc[i][j] = 0.f;
}

__device__ __forceinline__ float warp_sum(float v) {
    #pragma unroll
    for (int off = 16; off > 0; off >>= 1)
        v += __shfl_xor_sync(0xffffffffu, v, off);
    return v;
}

__global__ __launch_bounds__(256, 3)
void k_node(const int* __restrict__ node_id, const float* __restrict__ emb,
            const float* __restrict__ iW1, const float* __restrict__ ib1,
            const float* __restrict__ iW2, const float* __restrict__ ib2,
            const float* __restrict__ iW3, const float* __restrict__ ib3,
            const float* __restrict__ tW1, const float* __restrict__ tb1,
            const float* __restrict__ tW2, const float* __restrict__ tb2,
            const float* __restrict__ tW3, const float* __restrict__ tb3,
            const float* __restrict__ cW,  const float* __restrict__ cb,
            const float* __restrict__ fW,  const float* __restrict__ attn_a,
            int N) {
    extern __shared__ char smem_raw[];
    SmemT& s = *reinterpret_cast<SmemT*>(smem_raw);
    int tid = threadIdx.x;
    int c = tid & 31, r = tid >> 5;
    int base = blockIdx.x * 32;

    #pragma unroll
    for (int it = 0; it < 4; ++it) {
        int idx = tid + it * 256;
        int n = idx >> 5, c4 = idx & 31;
        int gn = base + n;
        int nid = (gn < N) ? node_id[gn] : 0;
        *(float4*)&s.E[n][c4 * 4] = *(const float4*)&emb[(size_t)nid * 128 + c4 * 4];
        float4 iv = make_float4(0.f, 0.f, 0.f, 0.f);
        float4 tv = make_float4(0.f, 0.f, 0.f, 0.f);
        if (gn < N) {
            iv = *(const float4*)&g_img_f[(size_t)gn * 128 + c4 * 4];
            tv = *(const float4*)&g_txt_f[(size_t)gn * 128 + c4 * 4];
        }
        *(float4*)&s.A[n][c4 * 4] = iv;
        *(float4*)&s.B[n][c4 * 4] = tv;
    }
    __syncthreads();

    float acc[4][4];

    zero_acc(acc);
    gemm32(iW1,             s.E, acc, r, c);
    gemm32(iW1 + 128 * 128, s.A, acc, r, c);
    {
        float4 b = __ldg((const float4*)&ib1[c * 4]);
        #pragma unroll
        for (int i = 0; i < 4; ++i) {
            s.H[r * 4 + i][c * 4 + 0] = fmaxf(acc[i][0] + b.x, 0.f);
            s.H[r * 4 + i][c * 4 + 1] = fmaxf(acc[i][1] + b.y, 0.f);
            s.H[r * 4 + i][c * 4 + 2] = fmaxf(acc[i][2] + b.z, 0.f);
            s.H[r * 4 + i][c * 4 + 3] = fmaxf(acc[i][3] + b.w, 0.f);
        }
    }
    __syncthreads();

    zero_acc(acc);
    gemm32(iW2, s.H, acc, r, c);
    {
        float4 b2 = __ldg((const float4*)&ib2[c * 4]);
        float4 w3 = __ldg((const float4*)&iW3[c * 4]);
        float b3 = __ldg(ib3);
        #pragma unroll
        for (int i = 0; i < 4; ++i) {
            float loc = fmaxf(acc[i][0] + b2.x, 0.f) * w3.x
                      + fmaxf(acc[i][1] + b2.y, 0.f) * w3.y
                      + fmaxf(acc[i][2] + b2.z, 0.f) * w3.z
                      + fmaxf(acc[i][3] + b2.w, 0.f) * w3.w;
            loc = warp_sum(loc);
            if (c == 0) s.g[r * 4 + i] = 1.f / (1.f + expf(-(loc + b3)));
        }
    }
    __syncthreads();

    #pragma unroll
    for (int i = 0; i < 4; ++i) {
        float gv = s.g[r * 4 + i];
        float4 av = *(const float4*)&s.A[r * 4 + i][c * 4];
        float4 ev = *(const float4*)&s.E[r * 4 + i][c * 4];
        av.x = gv * av.x + (1.f - gv) * ev.x;
        av.y = gv * av.y + (1.f - gv) * ev.y;
        av.z = gv * av.z + (1.f - gv) * ev.z;
        av.w = gv * av.w + (1.f - gv) * ev.w;
        *(float4*)&s.A[r * 4 + i][c * 4] = av;
    }

    zero_acc(acc);
    gemm32(tW1,             s.E, acc, r, c);
    gemm32(tW1 + 128 * 128, s.B, acc, r, c);
    {
        float4 b = __ldg((const float4*)&tb1[c * 4]);
        #pragma unroll
        for (int i = 0; i < 4; ++i) {
            s.H[r * 4 + i][c * 4 + 0] = fmaxf(acc[i][0] + b.x, 0.f);
            s.H[r * 4 + i][c * 4 + 1] = fmaxf(acc[i][1] + b.y, 0.f);
            s.H[r * 4 + i][c * 4 + 2] = fmaxf(acc[i][2] + b.z, 0.f);
            s.H[r * 4 + i][c * 4 + 3] = fmaxf(acc[i][3] + b.w, 0.f);
        }
    }
    __syncthreads();

    zero_acc(acc);
    gemm32(tW2, s.H, acc, r, c);
    {
        float4 b2 = __ldg((const float4*)&tb2[c * 4]);
        float4 w3 = __ldg((const float4*)&tW3[c * 4]);
        float b3 = __ldg(tb3);
        #pragma unroll
        for (int i = 0; i < 4; ++i) {
            float loc = fmaxf(acc[i][0] + b2.x, 0.f) * w3.x
                      + fmaxf(acc[i][1] + b2.y, 0.f) * w3.y
                      + fmaxf(acc[i][2] + b2.z, 0.f) * w3.z
                      + fmaxf(acc[i][3] + b2.w, 0.f) * w3.w;
            loc = warp_sum(loc);
            if (c == 0) s.g[r * 4 + i] = 1.f / (1.f + expf(-(loc + b3)));
        }
    }
    __syncthreads();

    #pragma unroll
    for (int i = 0; i < 4; ++i) {
        float gv = s.g[r * 4 + i];
        float4 bv = *(const float4*)&s.B[r * 4 + i][c * 4];
        float4 ev = *(const float4*)&s.E[r * 4 + i][c * 4];
        bv.x = gv * bv.x + (1.f - gv) * ev.x;
        bv.y = gv * bv.y + (1.f - gv) * ev.y;
        bv.z = gv * bv.z + (1.f - gv) * ev.z;
        bv.w = gv * bv.w + (1.f - gv) * ev.w;
        *(float4*)&s.B[r * 4 + i][c * 4] = bv;
    }
    __syncthreads();

    zero_acc(acc);
    gemm32(cW,             s.A, acc, r, c);
    gemm32(cW + 128 * 128, s.B, acc, r, c);
    {
        float4 b = __ldg((const float4*)&cb[c * 4]);
        #pragma unroll
        for (int i = 0; i < 4; ++i) {
            float4 av = *(const float4*)&s.A[r * 4 + i][c * 4];
            float4 bv = *(const float4*)&s.B[r * 4 + i][c * 4];
            float g0 = acc[i][0] + b.x;
            float g1 = acc[i][1] + b.y;
            float g2 = acc[i][2] + b.z;
            float g3 = acc[i][3] + b.w;
            s.H[r * 4 + i][c * 4 + 0] = g0 * av.x + (1.f - g0) * bv.x;
            s.H[r * 4 + i][c * 4 + 1] = g1 * av.y + (1.f - g1) * bv.y;
            s.H[r * 4 + i][c * 4 + 2] = g2 * av.z + (1.f - g2) * bv.z;
            s.H[r * 4 + i][c * 4 + 3] = g3 * av.w + (1.f - g3) * bv.w;
        }
    }
    __syncthreads();

    zero_acc(acc);
    gemm32(fW, s.H, acc, r, c);
    {
        float4 a1 = __ldg((const float4*)&attn_a[c * 4]);
        float4 a2 = __ldg((const float4*)&attn_a[128 + c * 4]);
        #pragma unroll
        for (int i = 0; i < 4; ++i) {
            int gn = base + r * 4 + i;
            if (gn < N) {
                float4 zv = make_float4(acc[i][0], acc[i][1], acc[i][2], acc[i][3]);
                *(float4*)&g_z[(size_t)gn * 128 + c * 4] = zv;
            }
            float l1 = acc[i][0] * a1.x + acc[i][1] * a1.y + acc[i][2] * a1.z + acc[i][3] * a1.w;
            float l2 = acc[i][0] * a2.x + acc[i][1] * a2.y + acc[i][2] * a2.z + acc[i][3] * a2.w;
            l1 = warp_sum(l1);
            l2 = warp_sum(l2);
            if (c == 0 && gn < N) { g_esrc[gn] = l1; g_edst[gn] = l2; }
        }
    }
}

// ---------------- edge phase ----------------
__device__ __forceinline__ void atomicMaxF(float* addr, float v) {
    if (v >= 0.f) atomicMax((int*)addr, __float_as_int(v));
    else          atomicMin((unsigned int*)addr, __float_as_uint(v));
}

__global__ void k_edge_max(const int* __restrict__ src, const int* __restrict__ dst, int E) {
    int i = blockIdx.x * blockDim.x + threadIdx.x;
    if (i >= E) return;
    float e = g_esrc[src[i]] + g_edst[dst[i]];
    e = (e >= 0.f) ? e : 0.01f * e;
    g_e[i] = e;
    atomicMaxF(&g_emax[dst[i]], e);
}

__global__ void k_edge_exp(const int* __restrict__ dst, int E) {
    int i = blockIdx.x * blockDim.x + threadIdx.x;
    if (i >= E) return;
    int d = dst[i];
    float ex = expf(g_e[i] - g_emax[d]);
    g_e[i] = ex;
    atomicAdd(&g_denom[d], ex);
}

__device__ __forceinline__ void redAdd4(float* addr, float4 v) {
    asm volatile("red.global.add.v4.f32 [%0], {%1, %2, %3, %4};"
                 :: "l"(addr), "f"(v.x), "f"(v.y), "f"(v.z), "f"(v.w) : "memory");
}

__global__ void k_edge_agg(const int* __restrict__ src, const int* __restrict__ dst,
                           float* __restrict__ out, int E) {
    int w = (int)((blockIdx.x * (size_t)blockDim.x + threadIdx.x) >> 5);
    int lane = threadIdx.x & 31;
    if (w >= E) return;
    int sN = src[w], d = dst[w];
    float alpha = g_e[w] / fmaxf(g_denom[d], 1e-20f);
    float4 zv = *(const float4*)&g_z[(size_t)sN * 128 + lane * 4];
    zv.x *= alpha; zv.y *= alpha; zv.z *= alpha; zv.w *= alpha;
    redAdd4(out + (size_t)d * 128 + lane * 4, zv);
}

// ---------------- launch ----------------
extern "C" void kernel_launch(void* const* d_in, const int* in_sizes, int n_in,
                              void* d_out, int out_size) {
    const int*   node_id = (const int*)  d_in[0];
    const float* img_h   = (const float*)d_in[1];
    const float* txt_h   = (const float*)d_in[2];
    const int*   src     = (const int*)  d_in[3];
    const int*   dst     = (const int*)  d_in[4];
    const float* emb     = (const float*)d_in[5];
    const float* W_img   = (const float*)d_in[6];
    const float* iW1     = (const float*)d_in[7];
    const float* ib1     = (const float*)d_in[8];
    const float* iW2     = (const float*)d_in[9];
    const float* ib2     = (const float*)d_in[10];
    const float* iW3     = (const float*)d_in[11];
    const float* ib3     = (const float*)d_in[12];
    const float* W_txt   = (const float*)d_in[13];
    const float* tW1     = (const float*)d_in[14];
    const float* tb1     = (const float*)d_in[15];
    const float* tW2     = (const float*)d_in[16];
    const float* tb2     = (const float*)d_in[17];
    const float* tW3     = (const float*)d_in[18];
    const float* tb3     = (const float*)d_in[19];
    const float* cW      = (const float*)d_in[20];
    const float* cb      = (const float*)d_in[21];
    const float* fW      = (const float*)d_in[22];
    const float* attn_a  = (const float*)d_in[23];

    int N = in_sizes[0];
    int E = in_sizes[3];
    int IMG_D = in_sizes[1] / N;
    int TXT_D = in_sizes[2] / N;
    float* out = (float*)d_out;

    float *p_img_f, *p_txt_f;
    cudaGetSymbolAddress((void**)&p_img_f, g_img_f);
    cudaGetSymbolAddress((void**)&p_txt_f, g_txt_f);

    cudaFuncSetAttribute(k_node, cudaFuncAttributeMaxDynamicSharedMemorySize, NODE_SMEM_BYTES);
    cudaFuncSetAttribute(k_mma_gemm, cudaFuncAttributeMaxDynamicSharedMemorySize, MMA_SMEM_BYTES);

    k_init<<<(N * HID + 255) / 256, 256>>>(out, N * HID, N);

    k_mma_gemm<<<(N + 127) / 128, 256, MMA_SMEM_BYTES>>>(img_h, W_img, p_img_f, N, IMG_D);
    k_mma_gemm<<<(N + 127) / 128, 256, MMA_SMEM_BYTES>>>(txt_h, W_txt, p_txt_f, N, TXT_D);

    k_node<<<(N + 31) / 32, 256, NODE_SMEM_BYTES>>>(
        node_id, emb,
        iW1, ib1, iW2, ib2, iW3, ib3,
        tW1, tb1, tW2, tb2, tW3, tb3,
        cW, cb, fW, attn_a, N);

    k_edge_max<<<(E + 255) / 256, 256>>>(src, dst, E);
    k_edge_exp<<<(E + 255) / 256, 256>>>(dst, E);
    k_edge_agg<<<(E * 32 + 255) / 256, 256>>>(src, dst, out, E);
}

// round 4
// speedup vs baseline: 2.1398x; 1.4870x over previous
#include <cuda_runtime.h>
#include <math_constants.h>

#define NN 50000
#define NE 800000
#define HID 128

// ---------------- scratch ----------------
__device__ float g_img_f[NN * HID];
__device__ float g_txt_f[NN * HID];
__device__ float g_z[NN * HID];
__device__ float g_esrc[NN];
__device__ float g_edst[NN];
__device__ float g_emax[NN];
__device__ float g_denom[NN];
__device__ float g_e[NE];

// ---------------- init ----------------
__global__ void k_init(float* __restrict__ out, int n_out, int n_nodes) {
    int i = blockIdx.x * blockDim.x + threadIdx.x;
    if (i < n_out) out[i] = 0.f;
    if (i < n_nodes) { g_emax[i] = -CUDART_INF_F; g_denom[i] = 0.f; }
}

// ---------------- tf32 helpers ----------------
__device__ __forceinline__ unsigned cvt_tf32(float x) {
    unsigned r; asm("cvt.rna.tf32.f32 %0, %1;" : "=r"(r) : "f"(x)); return r;
}
__device__ __forceinline__ void mma_tf32(float c[4], unsigned a0, unsigned a1,
                                         unsigned a2, unsigned a3,
                                         unsigned b0, unsigned b1) {
    asm volatile(
        "mma.sync.aligned.m16n8k8.row.col.f32.tf32.tf32.f32 "
        "{%0,%1,%2,%3}, {%4,%5,%6,%7}, {%8,%9}, {%0,%1,%2,%3};"
        : "+f"(c[0]), "+f"(c[1]), "+f"(c[2]), "+f"(c[3])
        : "r"(a0), "r"(a1), "r"(a2), "r"(a3), "r"(b0), "r"(b1));
}

// ================= big input GEMMs: 3xTF32, conflict-free smem =================
#define AMLD 36    // A tiles [m][k], 4m+k bank spread -> conflict-free frags
#define BNLD 132   // B tiles [k][n] padded, 4k+n spread -> conflict-free frags

struct MmaSmem {
    unsigned Ahi[128][AMLD];
    unsigned Alo[128][AMLD];
    unsigned Bhi[32][BNLD];
    unsigned Blo[32][BNLD];
};
#define MMA_SMEM_BYTES ((int)sizeof(MmaSmem))

__global__ __launch_bounds__(256, 2)
void k_mma_gemm(const float* __restrict__ Ai, const float* __restrict__ At,
                const float* __restrict__ Bi, const float* __restrict__ Bt,
                float* __restrict__ Ci, float* __restrict__ Ct,
                int M, int Ki, int Kt) {
    extern __shared__ char smem_raw[];
    MmaSmem& s = *reinterpret_cast<MmaSmem*>(smem_raw);
    int sel = blockIdx.y;
    const float* A = sel ? At : Ai;
    const float* B = sel ? Bt : Bi;
    float*       C = sel ? Ct : Ci;
    int K = sel ? Kt : Ki;

    int tid  = threadIdx.x;
    int warp = tid >> 5, lane = tid & 31;
    int wm = warp & 1;          // 0..1 : 64-row slab
    int wn = warp >> 1;         // 0..3 : 32-col slab
    int grp = lane >> 2, q = lane & 3;
    int m0 = blockIdx.x * 128;

    float acc[4][4][4];
    #pragma unroll
    for (int i = 0; i < 4; ++i)
        #pragma unroll
        for (int j = 0; j < 4; ++j)
            #pragma unroll
            for (int k = 0; k < 4; ++k) acc[i][j][k] = 0.f;

    #pragma unroll 1
    for (int k0 = 0; k0 < K; k0 += 32) {
        // ---- stage A tile 128x32 -> [m][k], uint4 stores ----
        #pragma unroll
        for (int i = 0; i < 4; ++i) {
            int f4 = tid + i * 256;           // 0..1023
            int r = f4 >> 3, c4 = f4 & 7;
            float4 v = make_float4(0.f, 0.f, 0.f, 0.f);
            if (m0 + r < M) v = *(const float4*)&A[(size_t)(m0 + r) * K + k0 + c4 * 4];
            float vv[4] = {v.x, v.y, v.z, v.w};
            unsigned hi4[4], lo4[4];
            #pragma unroll
            for (int j = 0; j < 4; ++j) {
                hi4[j] = cvt_tf32(vv[j]);
                lo4[j] = cvt_tf32(vv[j] - __uint_as_float(hi4[j]));
            }
            *(uint4*)&s.Ahi[r][c4 * 4] = make_uint4(hi4[0], hi4[1], hi4[2], hi4[3]);
            *(uint4*)&s.Alo[r][c4 * 4] = make_uint4(lo4[0], lo4[1], lo4[2], lo4[3]);
        }
        // ---- stage B tile 32x128 -> [k][n] padded ----
        #pragma unroll
        for (int i = 0; i < 4; ++i) {
            int f4 = tid + i * 256;
            int kk = f4 >> 5, c = f4 & 31;
            float4 v = *(const float4*)&B[(size_t)(k0 + kk) * 128 + c * 4];
            float vv[4] = {v.x, v.y, v.z, v.w};
            unsigned hi4[4], lo4[4];
            #pragma unroll
            for (int j = 0; j < 4; ++j) {
                hi4[j] = cvt_tf32(vv[j]);
                lo4[j] = cvt_tf32(vv[j] - __uint_as_float(hi4[j]));
            }
            *(uint4*)&s.Bhi[kk][c * 4] = make_uint4(hi4[0], hi4[1], hi4[2], hi4[3]);
            *(uint4*)&s.Blo[kk][c * 4] = make_uint4(lo4[0], lo4[1], lo4[2], lo4[3]);
        }
        __syncthreads();

        #pragma unroll
        for (int kc = 0; kc < 4; ++kc) {
            int kq = kc * 8 + q;
            unsigned af[4][4], bh[4][2], bl[4][2];
            #pragma unroll
            for (int mt = 0; mt < 4; ++mt) {
                int m = wm * 64 + mt * 16 + grp;
                af[mt][0] = s.Ahi[m][kq];
                af[mt][1] = s.Ahi[m + 8][kq];
                af[mt][2] = s.Ahi[m][kq + 4];
                af[mt][3] = s.Ahi[m + 8][kq + 4];
            }
            #pragma unroll
            for (int nt = 0; nt < 4; ++nt) {
                int n = wn * 32 + nt * 8 + grp;
                bh[nt][0] = s.Bhi[kq][n];  bh[nt][1] = s.Bhi[kq + 4][n];
                bl[nt][0] = s.Blo[kq][n];  bl[nt][1] = s.Blo[kq + 4][n];
            }
            #pragma unroll
            for (int mt = 0; mt < 4; ++mt)
                #pragma unroll
                for (int nt = 0; nt < 4; ++nt) {
                    mma_tf32(acc[mt][nt], af[mt][0], af[mt][1], af[mt][2], af[mt][3],
                             bh[nt][0], bh[nt][1]);
                    mma_tf32(acc[mt][nt], af[mt][0], af[mt][1], af[mt][2], af[mt][3],
                             bl[nt][0], bl[nt][1]);
                }
            #pragma unroll
            for (int mt = 0; mt < 4; ++mt) {
                int m = wm * 64 + mt * 16 + grp;
                af[mt][0] = s.Alo[m][kq];
                af[mt][1] = s.Alo[m + 8][kq];
                af[mt][2] = s.Alo[m][kq + 4];
                af[mt][3] = s.Alo[m + 8][kq + 4];
            }
            #pragma unroll
            for (int mt = 0; mt < 4; ++mt)
                #pragma unroll
                for (int nt = 0; nt < 4; ++nt)
                    mma_tf32(acc[mt][nt], af[mt][0], af[mt][1], af[mt][2], af[mt][3],
                             bh[nt][0], bh[nt][1]);
        }
        __syncthreads();
    }

    #pragma unroll
    for (int mt = 0; mt < 4; ++mt) {
        int m = m0 + wm * 64 + mt * 16 + grp;
        #pragma unroll
        for (int nt = 0; nt < 4; ++nt) {
            int n = wn * 32 + nt * 8 + 2 * q;
            if (m < M)
                *(float2*)&C[(size_t)m * 128 + n] = make_float2(acc[mt][nt][0], acc[mt][nt][1]);
            if (m + 8 < M)
                *(float2*)&C[(size_t)(m + 8) * 128 + n] = make_float2(acc[mt][nt][2], acc[mt][nt][3]);
        }
    }
}

// ================= fused per-node pipeline: tensor-core version =================
// 32 nodes/block, 256 threads = 8 warps. Warp w owns output cols w*16..w*16+15
// (2 n-tiles of 8); all 32 rows = 2 m-tiles of 16. X in fp32 smem (LD 132:
// A-frag lane bank = 4*grp+q = lane -> conflict-free). W via __ldg.
#define XLD 132

struct SmemN {
    float E[32][XLD];
    float A[32][XLD];
    float B[32][XLD];
    float H[32][XLD];
    float red[32][8][2];
    float g[32];
};
#define NODE_SMEM_BYTES ((int)sizeof(SmemN))

__device__ __forceinline__ void zacc(float acc[2][2][4]) {
    #pragma unroll
    for (int i = 0; i < 2; ++i)
        #pragma unroll
        for (int j = 0; j < 2; ++j)
            #pragma unroll
            for (int k = 0; k < 4; ++k) acc[i][j][k] = 0.f;
}

// acc += X(32x128) @ W(128x128), single tf32 (gate passes)
__device__ __forceinline__ void npass1(const float (*__restrict__ X)[XLD],
                                       const float* __restrict__ W,
                                       float acc[2][2][4], int n0, int grp, int q) {
    #pragma unroll 4
    for (int kc = 0; kc < 16; ++kc) {
        int k0 = kc * 8;
        unsigned a[2][4];
        #pragma unroll
        for (int mt = 0; mt < 2; ++mt) {
            a[mt][0] = cvt_tf32(X[mt * 16 + grp    ][k0 + q]);
            a[mt][1] = cvt_tf32(X[mt * 16 + grp + 8][k0 + q]);
            a[mt][2] = cvt_tf32(X[mt * 16 + grp    ][k0 + q + 4]);
            a[mt][3] = cvt_tf32(X[mt * 16 + grp + 8][k0 + q + 4]);
        }
        unsigned b[2][2];
        #pragma unroll
        for (int nt = 0; nt < 2; ++nt) {
            b[nt][0] = cvt_tf32(__ldg(&W[(k0 + q)     * 128 + n0 + nt * 8 + grp]));
            b[nt][1] = cvt_tf32(__ldg(&W[(k0 + q + 4) * 128 + n0 + nt * 8 + grp]));
        }
        #pragma unroll
        for (int mt = 0; mt < 2; ++mt)
            #pragma unroll
            for (int nt = 0; nt < 2; ++nt)
                mma_tf32(acc[mt][nt], a[mt][0], a[mt][1], a[mt][2], a[mt][3],
                         b[nt][0], b[nt][1]);
    }
}

// acc += X @ W with 3xTF32 compensation (value-critical passes)
__device__ __forceinline__ void npass3(const float (*__restrict__ X)[XLD],
                                       const float* __restrict__ W,
                                       float acc[2][2][4], int n0, int grp, int q) {
    #pragma unroll 2
    for (int kc = 0; kc < 16; ++kc) {
        int k0 = kc * 8;
        unsigned ah[2][4], al[2][4];
        #pragma unroll
        for (int mt = 0; mt < 2; ++mt) {
            float x0 = X[mt * 16 + grp    ][k0 + q];
            float x1 = X[mt * 16 + grp + 8][k0 + q];
            float x2 = X[mt * 16 + grp    ][k0 + q + 4];
            float x3 = X[mt * 16 + grp + 8][k0 + q + 4];
            ah[mt][0] = cvt_tf32(x0); al[mt][0] = cvt_tf32(x0 - __uint_as_float(ah[mt][0]));
            ah[mt][1] = cvt_tf32(x1); al[mt][1] = cvt_tf32(x1 - __uint_as_float(ah[mt][1]));
            ah[mt][2] = cvt_tf32(x2); al[mt][2] = cvt_tf32(x2 - __uint_as_float(ah[mt][2]));
            ah[mt][3] = cvt_tf32(x3); al[mt][3] = cvt_tf32(x3 - __uint_as_float(ah[mt][3]));
        }
        unsigned bh[2][2], bl[2][2];
        #pragma unroll
        for (int nt = 0; nt < 2; ++nt) {
            float w0 = __ldg(&W[(k0 + q)     * 128 + n0 + nt * 8 + grp]);
            float w1 = __ldg(&W[(k0 + q + 4) * 128 + n0 + nt * 8 + grp]);
            bh[nt][0] = cvt_tf32(w0); bl[nt][0] = cvt_tf32(w0 - __uint_as_float(bh[nt][0]));
            bh[nt][1] = cvt_tf32(w1); bl[nt][1] = cvt_tf32(w1 - __uint_as_float(bh[nt][1]));
        }
        #pragma unroll
        for (int mt = 0; mt < 2; ++mt)
            #pragma unroll
            for (int nt = 0; nt < 2; ++nt) {
                mma_tf32(acc[mt][nt], ah[mt][0], ah[mt][1], ah[mt][2], ah[mt][3],
                         bh[nt][0], bh[nt][1]);
                mma_tf32(acc[mt][nt], ah[mt][0], ah[mt][1], ah[mt][2], ah[mt][3],
                         bl[nt][0], bl[nt][1]);
                mma_tf32(acc[mt][nt], al[mt][0], al[mt][1], al[mt][2], al[mt][3],
                         bh[nt][0], bh[nt][1]);
            }
    }
}

// relu(acc + bias) -> s.H
__device__ __forceinline__ void relu_store(SmemN& s, float acc[2][2][4],
                                           const float* __restrict__ bp,
                                           int n0, int grp, int q) {
    #pragma unroll
    for (int nt = 0; nt < 2; ++nt) {
        int col = n0 + nt * 8 + 2 * q;
        float2 b = __ldg((const float2*)&bp[col]);
        #pragma unroll
        for (int mt = 0; mt < 2; ++mt) {
            int r1 = mt * 16 + grp;
            s.H[r1][col]     = fmaxf(acc[mt][nt][0] + b.x, 0.f);
            s.H[r1][col + 1] = fmaxf(acc[mt][nt][1] + b.y, 0.f);
            s.H[r1 + 8][col]     = fmaxf(acc[mt][nt][2] + b.x, 0.f);
            s.H[r1 + 8][col + 1] = fmaxf(acc[mt][nt][3] + b.y, 0.f);
        }
    }
}

// relu(acc+b2)@w3 + b3 -> sigmoid -> s.g[32]  (two internal barriers)
__device__ __forceinline__ void gate_finish(SmemN& s, float acc[2][2][4],
                                            const float* __restrict__ b2p,
                                            const float* __restrict__ w3p,
                                            const float* __restrict__ b3p,
                                            int n0, int grp, int q, int warp, int tid) {
    float part[4] = {0.f, 0.f, 0.f, 0.f};
    #pragma unroll
    for (int nt = 0; nt < 2; ++nt) {
        int col = n0 + nt * 8 + 2 * q;
        float2 b2 = __ldg((const float2*)&b2p[col]);
        float2 w3 = __ldg((const float2*)&w3p[col]);
        #pragma unroll
        for (int mt = 0; mt < 2; ++mt) {
            part[mt * 2 + 0] += fmaxf(acc[mt][nt][0] + b2.x, 0.f) * w3.x
                              + fmaxf(acc[mt][nt][1] + b2.y, 0.f) * w3.y;
            part[mt * 2 + 1] += fmaxf(acc[mt][nt][2] + b2.x, 0.f) * w3.x
                              + fmaxf(acc[mt][nt][3] + b2.y, 0.f) * w3.y;
        }
    }
    #pragma unroll
    for (int i = 0; i < 4; ++i) {
        part[i] += __shfl_xor_sync(0xffffffffu, part[i], 1);
        part[i] += __shfl_xor_sync(0xffffffffu, part[i], 2);
    }
    if (q == 0) {
        #pragma unroll
        for (int mt = 0; mt < 2; ++mt) {
            s.red[mt * 16 + grp][warp][0]     = part[mt * 2 + 0];
            s.red[mt * 16 + grp + 8][warp][0] = part[mt * 2 + 1];
        }
    }
    __syncthreads();
    if (tid < 32) {
        float v = 0.f;
        #pragma unroll
        for (int w = 0; w < 8; ++w) v += s.red[tid][w][0];
        s.g[tid] = 1.f / (1.f + expf(-(v + __ldg(b3p))));
    }
    __syncthreads();
}

__global__ __launch_bounds__(256, 3)
void k_node(const int* __restrict__ node_id, const float* __restrict__ emb,
            const float* __restrict__ iW1, const float* __restrict__ ib1,
            const float* __restrict__ iW2, const float* __restrict__ ib2,
            const float* __restrict__ iW3, const float* __restrict__ ib3,
            const float* __restrict__ tW1, const float* __restrict__ tb1,
            const float* __restrict__ tW2, const float* __restrict__ tb2,
            const float* __restrict__ tW3, const float* __restrict__ tb3,
            const float* __restrict__ cW,  const float* __restrict__ cb,
            const float* __restrict__ fW,  const float* __restrict__ attn_a,
            int N) {
    extern __shared__ char smem_raw[];
    SmemN& s = *reinterpret_cast<SmemN*>(smem_raw);
    int tid = threadIdx.x;
    int warp = tid >> 5, lane = tid & 31;
    int grp = lane >> 2, q = lane & 3;
    int n0 = warp * 16;
    int r8 = tid >> 5, c32 = tid & 31;   // elementwise-mixing layout
    int base = blockIdx.x * 32;

    // ---- load embed (gather) + img/txt features ----
    #pragma unroll
    for (int it = 0; it < 4; ++it) {
        int idx = tid + it * 256;             // float4 index 0..1023
        int n = idx >> 5, c4 = idx & 31;
        int gn = base + n;
        int nid = (gn < N) ? __ldg(&node_id[gn]) : 0;
        *(float4*)&s.E[n][c4 * 4] = *(const float4*)&emb[(size_t)nid * 128 + c4 * 4];
        float4 iv = make_float4(0.f, 0.f, 0.f, 0.f);
        float4 tv = make_float4(0.f, 0.f, 0.f, 0.f);
        if (gn < N) {
            iv = *(const float4*)&g_img_f[(size_t)gn * 128 + c4 * 4];
            tv = *(const float4*)&g_txt_f[(size_t)gn * 128 + c4 * 4];
        }
        *(float4*)&s.A[n][c4 * 4] = iv;
        *(float4*)&s.B[n][c4 * 4] = tv;
    }
    __syncthreads();

    float acc[2][2][4];

    // ==== img gate MLP ====
    zacc(acc);
    npass1(s.E, iW1, acc, n0, grp, q);
    npass1(s.A, iW1 + 128 * 128, acc, n0, grp, q);
    relu_store(s, acc, ib1, n0, grp, q);
    __syncthreads();

    zacc(acc);
    npass1(s.H, iW2, acc, n0, grp, q);
    gate_finish(s, acc, ib2, iW3, ib3, n0, grp, q, warp, tid);

    // ---- img_v -> s.A (elementwise, rows r8*4..+3, cols c32*4..+3) ----
    #pragma unroll
    for (int i = 0; i < 4; ++i) {
        float gv = s.g[r8 * 4 + i];
        float4 av = *(const float4*)&s.A[r8 * 4 + i][c32 * 4];
        float4 ev = *(const float4*)&s.E[r8 * 4 + i][c32 * 4];
        av.x = gv * av.x + (1.f - gv) * ev.x;
        av.y = gv * av.y + (1.f - gv) * ev.y;
        av.z = gv * av.z + (1.f - gv) * ev.z;
        av.w = gv * av.w + (1.f - gv) * ev.w;
        *(float4*)&s.A[r8 * 4 + i][c32 * 4] = av;
    }

    // ==== txt gate MLP ====
    zacc(acc);
    npass1(s.E, tW1, acc, n0, grp, q);
    npass1(s.B, tW1 + 128 * 128, acc, n0, grp, q);
    relu_store(s, acc, tb1, n0, grp, q);
    __syncthreads();

    zacc(acc);
    npass1(s.H, tW2, acc, n0, grp, q);
    gate_finish(s, acc, tb2, tW3, tb3, n0, grp, q, warp, tid);

    // ---- txt_v -> s.B ----
    #pragma unroll
    for (int i = 0; i < 4; ++i) {
        float gv = s.g[r8 * 4 + i];
        float4 bv = *(const float4*)&s.B[r8 * 4 + i][c32 * 4];
        float4 ev = *(const float4*)&s.E[r8 * 4 + i][c32 * 4];
        bv.x = gv * bv.x + (1.f - gv) * ev.x;
        bv.y = gv * bv.y + (1.f - gv) * ev.y;
        bv.z = gv * bv.z + (1.f - gv) * ev.z;
        bv.w = gv * bv.w + (1.f - gv) * ev.w;
        *(float4*)&s.B[r8 * 4 + i][c32 * 4] = bv;
    }
    __syncthreads();   // A,B final before comb reads them

    // ==== comb gate (linear) + h ==== (3-term: gate scales values directly)
    zacc(acc);
    npass3(s.A, cW, acc, n0, grp, q);
    npass3(s.B, cW + 128 * 128, acc, n0, grp, q);
    {
        #pragma unroll
        for (int nt = 0; nt < 2; ++nt) {
            int col = n0 + nt * 8 + 2 * q;
            float2 cbv = __ldg((const float2*)&cb[col]);
            #pragma unroll
            for (int mt = 0; mt < 2; ++mt) {
                int r1 = mt * 16 + grp, r2 = r1 + 8;
                float g0 = acc[mt][nt][0] + cbv.x;
                float g1 = acc[mt][nt][1] + cbv.y;
                float g2 = acc[mt][nt][2] + cbv.x;
                float g3 = acc[mt][nt][3] + cbv.y;
                float2 av1 = *(const float2*)&s.A[r1][col];
                float2 bv1 = *(const float2*)&s.B[r1][col];
                float2 av2 = *(const float2*)&s.A[r2][col];
                float2 bv2 = *(const float2*)&s.B[r2][col];
                s.H[r1][col]     = g0 * av1.x + (1.f - g0) * bv1.x;
                s.H[r1][col + 1] = g1 * av1.y + (1.f - g1) * bv1.y;
                s.H[r2][col]     = g2 * av2.x + (1.f - g2) * bv2.x;
                s.H[r2][col + 1] = g3 * av2.y + (1.f - g3) * bv2.y;
            }
        }
    }
    __syncthreads();

    // ==== z = h @ fc_W (3-term) ; z store + attention logits ====
    zacc(acc);
    npass3(s.H, fW, acc, n0, grp, q);
    {
        float p1[4] = {0.f, 0.f, 0.f, 0.f};
        float p2[4] = {0.f, 0.f, 0.f, 0.f};
        #pragma unroll
        for (int nt = 0; nt < 2; ++nt) {
            int col = n0 + nt * 8 + 2 * q;
            float2 a1 = __ldg((const float2*)&attn_a[col]);
            float2 a2 = __ldg((const float2*)&attn_a[128 + col]);
            #pragma unroll
            for (int mt = 0; mt < 2; ++mt) {
                int r1 = mt * 16 + grp, r2 = r1 + 8;
                int g1_ = base + r1, g2_ = base + r2;
                if (g1_ < N)
                    *(float2*)&g_z[(size_t)g1_ * 128 + col] =
                        make_float2(acc[mt][nt][0], acc[mt][nt][1]);
                if (g2_ < N)
                    *(float2*)&g_z[(size_t)g2_ * 128 + col] =
                        make_float2(acc[mt][nt][2], acc[mt][nt][3]);
                p1[mt * 2 + 0] += acc[mt][nt][0] * a1.x + acc[mt][nt][1] * a1.y;
                p1[mt * 2 + 1] += acc[mt][nt][2] * a1.x + acc[mt][nt][3] * a1.y;
                p2[mt * 2 + 0] += acc[mt][nt][0] * a2.x + acc[mt][nt][1] * a2.y;
                p2[mt * 2 + 1] += acc[mt][nt][2] * a2.x + acc[mt][nt][3] * a2.y;
            }
        }
        #pragma unroll
        for (int i = 0; i < 4; ++i) {
            p1[i] += __shfl_xor_sync(0xffffffffu, p1[i], 1);
            p1[i] += __shfl_xor_sync(0xffffffffu, p1[i], 2);
            p2[i] += __shfl_xor_sync(0xffffffffu, p2[i], 1);
            p2[i] += __shfl_xor_sync(0xffffffffu, p2[i], 2);
        }
        if (q == 0) {
            #pragma unroll
            for (int mt = 0; mt < 2; ++mt) {
                s.red[mt * 16 + grp][warp][0]     = p1[mt * 2 + 0];
                s.red[mt * 16 + grp + 8][warp][0] = p1[mt * 2 + 1];
                s.red[mt * 16 + grp][warp][1]     = p2[mt * 2 + 0];
                s.red[mt * 16 + grp + 8][warp][1] = p2[mt * 2 + 1];
            }
        }
        __syncthreads();
        if (tid < 32) {
            float v1 = 0.f, v2 = 0.f;
            #pragma unroll
            for (int w = 0; w < 8; ++w) { v1 += s.red[tid][w][0]; v2 += s.red[tid][w][1]; }
            int gn = base + tid;
            if (gn < N) { g_esrc[gn] = v1; g_edst[gn] = v2; }
        }
    }
}

// ---------------- edge phase ----------------
__device__ __forceinline__ void atomicMaxF(float* addr, float v) {
    if (v >= 0.f) atomicMax((int*)addr, __float_as_int(v));
    else          atomicMin((unsigned int*)addr, __float_as_uint(v));
}

__global__ void k_edge_max(const int* __restrict__ src, const int* __restrict__ dst, int E) {
    int i = blockIdx.x * blockDim.x + threadIdx.x;
    if (i >= E) return;
    float e = g_esrc[src[i]] + g_edst[dst[i]];
    e = (e >= 0.f) ? e : 0.01f * e;
    g_e[i] = e;
    atomicMaxF(&g_emax[dst[i]], e);
}

__global__ void k_edge_exp(const int* __restrict__ dst, int E) {
    int i = blockIdx.x * blockDim.x + threadIdx.x;
    if (i >= E) return;
    int d = dst[i];
    float ex = expf(g_e[i] - g_emax[d]);
    g_e[i] = ex;
    atomicAdd(&g_denom[d], ex);
}

__device__ __forceinline__ void redAdd4(float* addr, float4 v) {
    asm volatile("red.global.add.v4.f32 [%0], {%1, %2, %3, %4};"
                 :: "l"(addr), "f"(v.x), "f"(v.y), "f"(v.z), "f"(v.w) : "memory");
}

__global__ void k_edge_agg(const int* __restrict__ src, const int* __restrict__ dst,
                           float* __restrict__ out, int E) {
    int w = (int)((blockIdx.x * (size_t)blockDim.x + threadIdx.x) >> 5);
    int lane = threadIdx.x & 31;
    if (w >= E) return;
    int sN = src[w], d = dst[w];
    float alpha = g_e[w] / fmaxf(g_denom[d], 1e-20f);
    float4 zv = *(const float4*)&g_z[(size_t)sN * 128 + lane * 4];
    zv.x *= alpha; zv.y *= alpha; zv.z *= alpha; zv.w *= alpha;
    redAdd4(out + (size_t)d * 128 + lane * 4, zv);
}

// ---------------- launch ----------------
extern "C" void kernel_launch(void* const* d_in, const int* in_sizes, int n_in,
                              void* d_out, int out_size) {
    const int*   node_id = (const int*)  d_in[0];
    const float* img_h   = (const float*)d_in[1];
    const float* txt_h   = (const float*)d_in[2];
    const int*   src     = (const int*)  d_in[3];
    const int*   dst     = (const int*)  d_in[4];
    const float* emb     = (const float*)d_in[5];
    const float* W_img   = (const float*)d_in[6];
    const float* iW1     = (const float*)d_in[7];
    const float* ib1     = (const float*)d_in[8];
    const float* iW2     = (const float*)d_in[9];
    const float* ib2     = (const float*)d_in[10];
    const float* iW3     = (const float*)d_in[11];
    const float* ib3     = (const float*)d_in[12];
    const float* W_txt   = (const float*)d_in[13];
    const float* tW1     = (const float*)d_in[14];
    const float* tb1     = (const float*)d_in[15];
    const float* tW2     = (const float*)d_in[16];
    const float* tb2     = (const float*)d_in[17];
    const float* tW3     = (const float*)d_in[18];
    const float* tb3     = (const float*)d_in[19];
    const float* cW      = (const float*)d_in[20];
    const float* cb      = (const float*)d_in[21];
    const float* fW      = (const float*)d_in[22];
    const float* attn_a  = (const float*)d_in[23];

    int N = in_sizes[0];
    int E = in_sizes[3];
    int IMG_D = in_sizes[1] / N;
    int TXT_D = in_sizes[2] / N;
    float* out = (float*)d_out;

    float *p_img_f, *p_txt_f;
    cudaGetSymbolAddress((void**)&p_img_f, g_img_f);
    cudaGetSymbolAddress((void**)&p_txt_f, g_txt_f);

    cudaFuncSetAttribute(k_node, cudaFuncAttributeMaxDynamicSharedMemorySize, NODE_SMEM_BYTES);
    cudaFuncSetAttribute(k_mma_gemm, cudaFuncAttributeMaxDynamicSharedMemorySize, MMA_SMEM_BYTES);

    k_init<<<(N * HID + 255) / 256, 256>>>(out, N * HID, N);

    dim3 ggrid((N + 127) / 128, 2);
    k_mma_gemm<<<ggrid, 256, MMA_SMEM_BYTES>>>(img_h, txt_h, W_img, W_txt,
                                               p_img_f, p_txt_f, N, IMG_D, TXT_D);

    k_node<<<(N + 31) / 32, 256, NODE_SMEM_BYTES>>>(
        node_id, emb,
        iW1, ib1, iW2, ib2, iW3, ib3,
        tW1, tb1, tW2, tb2, tW3, tb3,
        cW, cb, fW, attn_a, N);

    k_edge_max<<<(E + 255) / 256, 256>>>(src, dst, E);
    k_edge_exp<<<(E + 255) / 256, 256>>>(dst, E);
    k_edge_agg<<<(E * 32 + 255) / 256, 256>>>(src, dst, out, E);
}